// round 6
// baseline (speedup 1.0000x reference)
#include <cuda_runtime.h>
#include <cuda_bf16.h>
#include <math.h>
#include <cstdint>

// ---------------------------------------------------------------------------
// Problem constants (fixed by the dataset's setup_inputs)
// ---------------------------------------------------------------------------
constexpr int B_  = 8;
constexpr int Q_  = 2048;
constexpr int D_  = 256;
constexpr int Hh  = 100;
constexpr int Ww  = 100;
constexpr int HW  = Hh * Ww;       // 10000
constexpr int NH  = 8;
constexpr int NP  = 4;
constexpr int DH  = D_ / NH;       // 32
constexpr int BQ  = B_ * Q_;       // 16384
constexpr int PN  = 128;           // padded projection width (64 off + 32 attn + pad)

// Scratch (allocation-free rule: __device__ globals)
__device__ float         g_values[(size_t)B_ * HW * D_];   // 81.9 MB
__device__ float         g_result[(size_t)BQ * D_];        // 16.8 MB
__device__ float         g_proj[(size_t)BQ * PN];          // 8.4 MB
__device__ __nv_bfloat16 g_WvalT_hi[D_ * D_], g_WvalT_lo[D_ * D_];
__device__ __nv_bfloat16 g_WoutT_hi[D_ * D_], g_WoutT_lo[D_ * D_];
__device__ float         g_Wcomb_f32[D_ * PN];             // [K=256][N=128]
__device__ float         g_bias_comb[PN];

// ---------------------------------------------------------------------------
// Helpers
// ---------------------------------------------------------------------------
__device__ __forceinline__ uint32_t smem_u32(const void* p) {
    uint32_t a;
    asm("{ .reg .u64 t; cvta.to.shared.u64 t, %1; cvt.u32.u64 %0, t; }" : "=r"(a) : "l"(p));
    return a;
}
// swizzle for 128B-row layouts: 16B-unit ^= (row & 7)
__device__ __forceinline__ uint32_t swz128(uint32_t off) { return off ^ ((off >> 3) & 0x70); }
// swizzle for 512B-row layouts: 16B-unit ^= (row & 7)
__device__ __forceinline__ uint32_t swz512(uint32_t off) { return off ^ ((off >> 5) & 0x70); }

__device__ __forceinline__ uint32_t pack2bf(float a, float b) {   // a -> low half
    __nv_bfloat162 t = __floats2bfloat162_rn(a, b);
    return *reinterpret_cast<uint32_t*>(&t);
}
__device__ __forceinline__ void bf_split(float x, float& hf, float& lf) {
    __nv_bfloat16 h = __float2bfloat16_rn(x);
    hf = __bfloat162float(h);
    lf = x - hf;
}

__device__ __forceinline__ void ldm_x4(uint32_t* r, uint32_t addr) {
    asm volatile("ldmatrix.sync.aligned.m8n8.x4.shared.b16 {%0,%1,%2,%3}, [%4];"
        : "=r"(r[0]), "=r"(r[1]), "=r"(r[2]), "=r"(r[3]) : "r"(addr));
}
__device__ __forceinline__ void mma_bf16(float* d, const uint32_t* a, const uint32_t* b) {
    asm volatile("mma.sync.aligned.m16n8k16.row.col.f32.bf16.bf16.f32 "
        "{%0,%1,%2,%3}, {%4,%5,%6,%7}, {%8,%9}, {%0,%1,%2,%3};"
        : "+f"(d[0]), "+f"(d[1]), "+f"(d[2]), "+f"(d[3])
        : "r"(a[0]), "r"(a[1]), "r"(a[2]), "r"(a[3]), "r"(b[0]), "r"(b[1]));
}

// ---------------------------------------------------------------------------
// bf16x3 GEMM via mma.sync: C[M,N] = A[M,256] @ (Bhi+Blo)[N,256]^T + bias
//   BM=128, BN=128. B (hi+lo, full K=256) resident in SMEM, loaded once.
//   A double-buffered in 64-bf16 K-chunks. 8 warps, warp tile 32x64.
//   3-term split: ah*bh + al*bh + ah*bl.
// SMEM: BH 64KB | BL 64KB | A bufs 2 x (AH 16KB + AL 16KB) = 192KB.
// ---------------------------------------------------------------------------
constexpr int SM_BH = 0;
constexpr int SM_BL = 65536;
constexpr int SM_A  = 131072;          // buf b: AH at +b*32768, AL at +b*32768+16384
constexpr int SMEM_GEMM = 196608;

__global__ __launch_bounds__(256, 1)
void gemm_bf16x3(const float* __restrict__ A,
                 const __nv_bfloat16* __restrict__ Bhi,
                 const __nv_bfloat16* __restrict__ Blo,
                 const float* __restrict__ bias,
                 float* __restrict__ C, int N)
{
    extern __shared__ char smem[];
    const uint32_t sb = smem_u32(smem);
    const int tid  = threadIdx.x;
    const int bm   = blockIdx.x * 128;
    const int bn   = blockIdx.y * 128;
    const int w    = tid >> 5;
    const int lane = tid & 31;
    const int wm   = (w & 3) * 32;
    const int wn   = (w >> 2) * 64;

    // A staging mapping: row = tid>>1, half = tid&1 (32 floats along the row)
    const int arow  = tid >> 1;
    const int ahalf = tid & 1;
    const float* Abase = A + (size_t)(bm + arow) * 256 + ahalf * 32;

    float acc[2][8][4];
    #pragma unroll
    for (int i = 0; i < 2; i++)
        #pragma unroll
        for (int j = 0; j < 8; j++)
            #pragma unroll
            for (int k = 0; k < 4; k++) acc[i][j][k] = 0.f;

    // ---- Prologue: load full B (hi+lo, [128 rows][512B]) into resident SMEM ----
    {
        const char* BhB = (const char*)(Bhi + (size_t)bn * 256);
        const char* BlB = (const char*)(Blo + (size_t)bn * 256);
        #pragma unroll
        for (int i = 0; i < 16; i++) {
            int u = i * 256 + tid;
            uint32_t off = (uint32_t)u * 16;           // row = u>>5, unit = u&31
            uint4 hv = *(const uint4*)(BhB + off);
            uint4 lv = *(const uint4*)(BlB + off);
            uint32_t so = swz512(off);
            *(uint4*)(smem + SM_BH + so) = hv;
            *(uint4*)(smem + SM_BL + so) = lv;
        }
    }

    float4 a_st[8];
    auto stageA = [&](int c) {
        #pragma unroll
        for (int j = 0; j < 8; j++)
            a_st[j] = *(const float4*)(Abase + c * 64 + j * 4);
    };
    auto cvtstoreA = [&](int buf) {
        char* bp = smem + SM_A + buf * 32768;
        #pragma unroll
        for (int j = 0; j < 4; j++) {
            float4 v0 = a_st[2 * j], v1 = a_st[2 * j + 1];
            float h0,l0,h1,l1,h2,l2,h3,l3,h4,l4,h5,l5,h6,l6,h7,l7;
            bf_split(v0.x,h0,l0); bf_split(v0.y,h1,l1); bf_split(v0.z,h2,l2); bf_split(v0.w,h3,l3);
            bf_split(v1.x,h4,l4); bf_split(v1.y,h5,l5); bf_split(v1.z,h6,l6); bf_split(v1.w,h7,l7);
            uint4 hv = { pack2bf(h0,h1), pack2bf(h2,h3), pack2bf(h4,h5), pack2bf(h6,h7) };
            uint4 lv = { pack2bf(l0,l1), pack2bf(l2,l3), pack2bf(l4,l5), pack2bf(l6,l7) };
            uint32_t off = swz128((uint32_t)(arow * 128 + ahalf * 64 + j * 16));
            *(uint4*)(bp + off)         = hv;
            *(uint4*)(bp + 16384 + off) = lv;
        }
    };
    auto compute = [&](int c, int buf) {
        const uint32_t aA = sb + SM_A + buf * 32768;
        #pragma unroll
        for (int ks = 0; ks < 4; ks++) {
            uint32_t ah[2][4], al_[2][4];
            #pragma unroll
            for (int mf = 0; mf < 2; mf++) {
                int m_loc = wm + mf * 16 + (lane & 15);
                int kbyte = (ks * 16 + (lane >> 4) * 8) * 2;
                uint32_t off = swz128((uint32_t)(m_loc * 128 + kbyte));
                ldm_x4(ah[mf],  aA + off);
                ldm_x4(al_[mf], aA + 16384 + off);
            }
            uint32_t bh[8][2], bl[8][2];
            #pragma unroll
            for (int nf = 0; nf < 4; nf++) {
                int g = lane >> 3, r = lane & 7;
                int n_loc  = wn + nf * 16 + ((g & 2) << 2) + r;   // +8 for g>=2
                int kbyte  = c * 128 + ks * 32 + (g & 1) * 16;
                uint32_t off = swz512((uint32_t)(n_loc * 512 + kbyte));
                uint32_t th[4], tl[4];
                ldm_x4(th, sb + SM_BH + off);
                ldm_x4(tl, sb + SM_BL + off);
                bh[2*nf][0]   = th[0]; bh[2*nf][1]   = th[1];
                bh[2*nf+1][0] = th[2]; bh[2*nf+1][1] = th[3];
                bl[2*nf][0]   = tl[0]; bl[2*nf][1]   = tl[1];
                bl[2*nf+1][0] = tl[2]; bl[2*nf+1][1] = tl[3];
            }
            #pragma unroll
            for (int mf = 0; mf < 2; mf++)
                #pragma unroll
                for (int n8 = 0; n8 < 8; n8++) {
                    mma_bf16(acc[mf][n8], ah[mf],  bh[n8]);
                    mma_bf16(acc[mf][n8], al_[mf], bh[n8]);
                    mma_bf16(acc[mf][n8], ah[mf],  bl[n8]);
                }
        }
    };

    stageA(0);
    cvtstoreA(0);
    __syncthreads();

    for (int c = 0; c < 4; c++) {
        if (c < 3) {
            stageA(c + 1);
            cvtstoreA((c + 1) & 1);
        }
        compute(c, c & 1);
        __syncthreads();
    }

    // Epilogue: direct global stores with bias (bias index = global column)
    #pragma unroll
    for (int mf = 0; mf < 2; mf++) {
        #pragma unroll
        for (int n8 = 0; n8 < 8; n8++) {
            int col = bn + wn + n8 * 8 + (lane & 3) * 2;
            int r0  = bm + wm + mf * 16 + (lane >> 2);
            float b0 = __ldg(bias + col);
            float b1 = __ldg(bias + col + 1);
            float2 v0 = { acc[mf][n8][0] + b0, acc[mf][n8][1] + b1 };
            float2 v1 = { acc[mf][n8][2] + b0, acc[mf][n8][3] + b1 };
            *(float2*)(C + (size_t)r0 * N + col)       = v0;
            *(float2*)(C + (size_t)(r0 + 8) * N + col) = v1;
        }
    }
}

// ---------------------------------------------------------------------------
// fp32 SGEMM (exact) for the projection: C[M,N] = A[M,K] @ W[K][N] + bias
// BM=128, BN=128, BK=8, 256 threads, 8x8 per thread. (R1-validated)
// ---------------------------------------------------------------------------
constexpr int S_BM = 128, S_BN = 128, S_BK = 8, S_TM = 8, S_TN = 8;
constexpr int S_AP = 4;

__global__ __launch_bounds__(256, 2)
void sgemm_bias_kernel(const float* __restrict__ A,
                       const float* __restrict__ W,
                       const float* __restrict__ bias,
                       float* __restrict__ C,
                       int M, int N, int K)
{
    __shared__ float As[S_BK * (S_BM + S_AP)];
    __shared__ float Bs[S_BK * S_BN];

    const int bm = blockIdx.y * S_BM;
    const int bn = blockIdx.x * S_BN;
    const int tid = threadIdx.x;
    const int tx = tid % (S_BN / S_TN);
    const int ty = tid / (S_BN / S_TN);
    const int arow  = tid >> 1;
    const int acol4 = (tid & 1) * 4;
    const int brow  = tid >> 5;
    const int bcol  = (tid & 31) * 4;

    float acc[S_TM][S_TN];
    #pragma unroll
    for (int i = 0; i < S_TM; i++)
        #pragma unroll
        for (int j = 0; j < S_TN; j++) acc[i][j] = 0.f;

    const float* Ab = A + (size_t)bm * K;

    for (int k0 = 0; k0 < K; k0 += S_BK) {
        float4 a4 = *(const float4*)(Ab + (size_t)arow * K + k0 + acol4);
        As[(acol4 + 0) * (S_BM + S_AP) + arow] = a4.x;
        As[(acol4 + 1) * (S_BM + S_AP) + arow] = a4.y;
        As[(acol4 + 2) * (S_BM + S_AP) + arow] = a4.z;
        As[(acol4 + 3) * (S_BM + S_AP) + arow] = a4.w;
        float4 b4 = *(const float4*)(W + (size_t)(k0 + brow) * N + bn + bcol);
        *(float4*)(&Bs[brow * S_BN + bcol]) = b4;
        __syncthreads();
        #pragma unroll
        for (int k = 0; k < S_BK; k++) {
            float ra[S_TM], rb[S_TN];
            #pragma unroll
            for (int i = 0; i < S_TM; i += 4)
                *(float4*)(&ra[i]) = *(const float4*)(&As[k * (S_BM + S_AP) + ty * S_TM + i]);
            #pragma unroll
            for (int j = 0; j < S_TN; j += 4)
                *(float4*)(&rb[j]) = *(const float4*)(&Bs[k * S_BN + tx * S_TN + j]);
            #pragma unroll
            for (int i = 0; i < S_TM; i++)
                #pragma unroll
                for (int j = 0; j < S_TN; j++)
                    acc[i][j] = fmaf(ra[i], rb[j], acc[i][j]);
        }
        __syncthreads();
    }

    float bs[S_TN];
    #pragma unroll
    for (int j = 0; j < S_TN; j++) bs[j] = bias[bn + tx * S_TN + j];
    #pragma unroll
    for (int i = 0; i < S_TM; i++) {
        float* crow = C + (size_t)(bm + ty * S_TM + i) * N + bn + tx * S_TN;
        #pragma unroll
        for (int j = 0; j < S_TN; j += 4) {
            float4 v;
            v.x = acc[i][j + 0] + bs[j + 0];
            v.y = acc[i][j + 1] + bs[j + 1];
            v.z = acc[i][j + 2] + bs[j + 2];
            v.w = acc[i][j + 3] + bs[j + 3];
            *(float4*)(crow + j) = v;
        }
    }
}

// ---------------------------------------------------------------------------
// Weight prep
// ---------------------------------------------------------------------------
__global__ void prep_wsplit(const float* __restrict__ W,        // [256][256]
                            __nv_bfloat16* __restrict__ hi,
                            __nv_bfloat16* __restrict__ lo)
{
    int n = blockIdx.x, k = threadIdx.x;
    float x = W[(size_t)k * 256 + n];
    float hf, lf; bf_split(x, hf, lf);
    hi[(size_t)n * 256 + k] = __float2bfloat16_rn(hf);
    lo[(size_t)n * 256 + k] = __float2bfloat16_rn(lf);
}

__global__ void prep_wcomb_f32(const float* __restrict__ W_off,   // [256][64]
                               const float* __restrict__ W_attn,  // [256][32]
                               const float* __restrict__ b_off,
                               const float* __restrict__ b_attn,
                               float* __restrict__ Wc,             // [256][128]
                               float* __restrict__ bias)
{
    int k = blockIdx.x, n = threadIdx.x;     // k < 256, n < 128
    float x = 0.f;
    if (n < 64)       x = W_off[(size_t)k * 64 + n];
    else if (n < 96)  x = W_attn[(size_t)k * 32 + (n - 64)];
    Wc[(size_t)k * PN + n] = x;
    if (k == 0) bias[n] = (n < 64) ? b_off[n] : ((n < 96) ? b_attn[n - 64] : 0.f);
}

// ---------------------------------------------------------------------------
// Sample: softmax + bilinear gather; projections precomputed in g_proj.
// One CTA of 256 threads per (b,q). Warp h = head h, lane = channel.
// ---------------------------------------------------------------------------
__global__ __launch_bounds__(256)
void sample_kernel(const float* __restrict__ refpts)
{
    const int bq = blockIdx.x;
    const int b  = bq / Q_;
    const int t  = threadIdx.x;

    __shared__ float offs[NH * NP * 2];   // 64
    __shared__ float attn[NH * NP];       // 32

    if (t < 96) {
        float v = g_proj[(size_t)bq * PN + t];
        if (t < 64) offs[t] = v;
        else        attn[t - 64] = v;
    }
    __syncthreads();

    if (t < NH) {
        float m = attn[t * NP];
        #pragma unroll
        for (int p = 1; p < NP; p++) m = fmaxf(m, attn[t * NP + p]);
        float e[NP], s = 0.f;
        #pragma unroll
        for (int p = 0; p < NP; p++) { e[p] = __expf(attn[t * NP + p] - m); s += e[p]; }
        float inv = 1.f / s;
        #pragma unroll
        for (int p = 0; p < NP; p++) attn[t * NP + p] = e[p] * inv;
    }
    __syncthreads();

    const int h = t >> 5;
    const int d = t & 31;
    const float rx = refpts[(size_t)bq * 2 + 0];
    const float ry = refpts[(size_t)bq * 2 + 1];
    const float* vb = g_values + (size_t)b * HW * D_ + h * DH + d;

    float acc = 0.f;
    #pragma unroll
    for (int p = 0; p < NP; p++) {
        float lx = fminf(fmaxf(rx + offs[(h * NP + p) * 2 + 0], 0.f), 1.f);
        float ly = fminf(fmaxf(ry + offs[(h * NP + p) * 2 + 1], 0.f), 1.f);
        float sx = lx * (float)(Ww - 1);
        float sy = ly * (float)(Hh - 1);
        int x0 = min(max((int)floorf(sx), 0), Ww - 1);
        int y0 = min(max((int)floorf(sy), 0), Hh - 1);
        int x1 = min(x0 + 1, Ww - 1);
        int y1 = min(y0 + 1, Hh - 1);
        float wx1 = sx - (float)x0, wx0 = 1.f - wx1;
        float wy1 = sy - (float)y0, wy0 = 1.f - wy1;

        float g00 = vb[(size_t)(y0 * Ww + x0) * D_];
        float g01 = vb[(size_t)(y1 * Ww + x0) * D_];
        float g10 = vb[(size_t)(y0 * Ww + x1) * D_];
        float g11 = vb[(size_t)(y1 * Ww + x1) * D_];

        float bil = g00 * (wx0 * wy0) + g01 * (wx0 * wy1)
                  + g10 * (wx1 * wy0) + g11 * (wx1 * wy1);
        acc = fmaf(attn[h * NP + p], bil, acc);
    }
    g_result[(size_t)bq * D_ + t] = acc;
}

// ---------------------------------------------------------------------------
// kernel_launch
// Inputs: 0=query 1=reference_points 2=input_flatten 3=h 4=w
//   5=W_off 6=b_off 7=W_attn 8=b_attn 9=W_val 10=b_val 11=W_out 12=b_out
// ---------------------------------------------------------------------------
extern "C" void kernel_launch(void* const* d_in, const int* in_sizes, int n_in,
                              void* d_out, int out_size)
{
    const float* query    = (const float*)d_in[0];
    const float* refpts   = (const float*)d_in[1];
    const float* in_flat  = (const float*)d_in[2];
    const float* W_off    = (const float*)d_in[5];
    const float* b_off    = (const float*)d_in[6];
    const float* W_attn   = (const float*)d_in[7];
    const float* b_attn   = (const float*)d_in[8];
    const float* W_val    = (const float*)d_in[9];
    const float* b_val    = (const float*)d_in[10];
    const float* W_out    = (const float*)d_in[11];
    const float* b_out    = (const float*)d_in[12];
    float* out = (float*)d_out;

    float *values_p, *result_p, *proj_p, *biasc_p, *wcomb_p;
    __nv_bfloat16 *wvh, *wvl, *woh, *wol;
    cudaGetSymbolAddress((void**)&values_p, g_values);
    cudaGetSymbolAddress((void**)&result_p, g_result);
    cudaGetSymbolAddress((void**)&proj_p,   g_proj);
    cudaGetSymbolAddress((void**)&biasc_p,  g_bias_comb);
    cudaGetSymbolAddress((void**)&wcomb_p,  g_Wcomb_f32);
    cudaGetSymbolAddress((void**)&wvh, g_WvalT_hi);
    cudaGetSymbolAddress((void**)&wvl, g_WvalT_lo);
    cudaGetSymbolAddress((void**)&woh, g_WoutT_hi);
    cudaGetSymbolAddress((void**)&wol, g_WoutT_lo);

    cudaFuncSetAttribute(gemm_bf16x3, cudaFuncAttributeMaxDynamicSharedMemorySize, SMEM_GEMM);

    // 0) weight prep (tiny)
    prep_wsplit<<<256, 256>>>(W_val, wvh, wvl);
    prep_wsplit<<<256, 256>>>(W_out, woh, wol);
    prep_wcomb_f32<<<256, 128>>>(W_off, W_attn, b_off, b_attn, wcomb_p, biasc_p);

    // 1) projections (fp32, exact): g_proj[16384,128] = query @ Wcomb + bias
    {
        dim3 grid(PN / S_BN, BQ / S_BM);   // (1, 128)
        sgemm_bias_kernel<<<grid, 256>>>(query, wcomb_p, biasc_p, proj_p, BQ, PN, D_);
    }

    // 2) values: g_values[80000,256] = input_flatten @ W_val + b_val
    {
        dim3 grid((B_ * HW) / 128, 2);
        gemm_bf16x3<<<grid, 256, SMEM_GEMM>>>(in_flat, wvh, wvl, b_val, values_p, D_);
    }

    // 3) softmax + bilinear sampling -> g_result[16384,256]
    sample_kernel<<<BQ, 256>>>(refpts);

    // 4) out = g_result @ W_out + b_out
    {
        dim3 grid(BQ / 128, 2);
        gemm_bf16x3<<<grid, 256, SMEM_GEMM>>>(result_p, woh, wol, b_out, out, D_);
    }
}

// round 8
// speedup vs baseline: 1.1170x; 1.1170x over previous
#include <cuda_runtime.h>
#include <cuda_bf16.h>
#include <math.h>
#include <cstdint>

// R8 == R7 re-run: R7 failed with "GB300 container failed twice" (no compiler or
// harness output). Kernel audit found no hang source (all loops bounded, no
// divergent barriers, cp.async ranges in-bounds) -> infra flake hypothesis.
// A second identical failure implicates cp.async; fallback is the R5 LDG path.

// ---------------------------------------------------------------------------
// Problem constants (fixed by the dataset's setup_inputs)
// ---------------------------------------------------------------------------
constexpr int B_  = 8;
constexpr int Q_  = 2048;
constexpr int D_  = 256;
constexpr int Hh  = 100;
constexpr int Ww  = 100;
constexpr int HW  = Hh * Ww;       // 10000
constexpr int NH  = 8;
constexpr int NP  = 4;
constexpr int DH  = D_ / NH;       // 32
constexpr int BQ  = B_ * Q_;       // 16384
constexpr int PN  = 128;           // padded projection width (64 off + 32 attn + pad)

// Scratch (allocation-free rule: __device__ globals)
__device__ float         g_values[(size_t)B_ * HW * D_];   // 81.9 MB
__device__ float         g_result[(size_t)BQ * D_];        // 16.8 MB
__device__ float         g_proj[(size_t)BQ * PN];          // 8.4 MB
__device__ __nv_bfloat16 g_WvalT_hi[D_ * D_], g_WvalT_lo[D_ * D_];
__device__ __nv_bfloat16 g_WoutT_hi[D_ * D_], g_WoutT_lo[D_ * D_];
__device__ __nv_bfloat16 g_Wcomb_hi[PN * D_], g_Wcomb_lo[PN * D_];
__device__ float         g_bias_comb[PN];

// ---------------------------------------------------------------------------
// Helpers
// ---------------------------------------------------------------------------
__device__ __forceinline__ uint32_t smem_u32(const void* p) {
    uint32_t a;
    asm("{ .reg .u64 t; cvta.to.shared.u64 t, %1; cvt.u32.u64 %0, t; }" : "=r"(a) : "l"(p));
    return a;
}
// swizzle for 128B-row layouts: 16B-unit ^= (row & 7)
__device__ __forceinline__ uint32_t swz128(uint32_t off) { return off ^ ((off >> 3) & 0x70); }

__device__ __forceinline__ uint32_t pack2bf(float a, float b) {   // a -> low half
    __nv_bfloat162 t = __floats2bfloat162_rn(a, b);
    return *reinterpret_cast<uint32_t*>(&t);
}
__device__ __forceinline__ void bf_split(float x, float& hf, float& lf) {
    __nv_bfloat16 h = __float2bfloat16_rn(x);
    hf = __bfloat162float(h);
    lf = x - hf;
}

__device__ __forceinline__ void ldm_x4(uint32_t* r, uint32_t addr) {
    asm volatile("ldmatrix.sync.aligned.m8n8.x4.shared.b16 {%0,%1,%2,%3}, [%4];"
        : "=r"(r[0]), "=r"(r[1]), "=r"(r[2]), "=r"(r[3]) : "r"(addr));
}
__device__ __forceinline__ void mma_bf16(float* d, const uint32_t* a, const uint32_t* b) {
    asm volatile("mma.sync.aligned.m16n8k16.row.col.f32.bf16.bf16.f32 "
        "{%0,%1,%2,%3}, {%4,%5,%6,%7}, {%8,%9}, {%0,%1,%2,%3};"
        : "+f"(d[0]), "+f"(d[1]), "+f"(d[2]), "+f"(d[3])
        : "r"(a[0]), "r"(a[1]), "r"(a[2]), "r"(a[3]), "r"(b[0]), "r"(b[1]));
}
#define CP_ASYNC16(dst, src) \
    asm volatile("cp.async.cg.shared.global [%0], [%1], 16;" :: "r"(dst), "l"(src))
#define CP_COMMIT()  asm volatile("cp.async.commit_group;" ::: "memory")
#define CP_WAIT0()   asm volatile("cp.async.wait_group 0;" ::: "memory")

// ---------------------------------------------------------------------------
// bf16x3 GEMM via mma.sync: C[M,N] = A[M,256] @ (Bhi+Blo)[N,256]^T + bias
//   BM=128, BN=64, BK=64 bf16 (4 chunks), double-buffered, 8 warps,
//   warp tile 32x32. 3-term split: ah*bh + al*bh + ah*bl.
//   B is a straight bf16 copy -> cp.async; A is fp32->bf16 split via regs.
// SMEM per buffer: AH 16K | AL 16K | BH 8K | BL 8K = 48KB; x2 = 96KB.
// -> 2 CTAs/SM.
// ---------------------------------------------------------------------------
constexpr int SB_AH = 0;
constexpr int SB_AL = 16384;
constexpr int SB_BH = 32768;
constexpr int SB_BL = 40960;
constexpr int SM_BUFSZ = 49152;
constexpr int SMEM_GEMM = 2 * SM_BUFSZ;   // 98304

__global__ __launch_bounds__(256, 2)
void gemm_bf16x3(const float* __restrict__ A,
                 const __nv_bfloat16* __restrict__ Bhi,
                 const __nv_bfloat16* __restrict__ Blo,
                 const float* __restrict__ bias,
                 float* __restrict__ C, int N)
{
    extern __shared__ char smem[];
    const uint32_t sb = smem_u32(smem);
    const int tid  = threadIdx.x;
    const int bm   = blockIdx.x * 128;
    const int bn   = blockIdx.y * 64;
    const int w    = tid >> 5;
    const int lane = tid & 31;
    const int wm   = (w & 3) * 32;
    const int wn   = (w >> 2) * 32;

    // A staging mapping: row = tid>>1, half = tid&1 (32 floats along the row)
    const int arow  = tid >> 1;
    const int ahalf = tid & 1;
    const float* Abase = A + (size_t)(bm + arow) * 256 + ahalf * 32;

    // B cp.async mapping: per chunk, hi and lo each 64 rows x 8 units
    const int brow = tid >> 3;            // used with i*32 row offset
    const int bjj  = tid & 7;
    const char* BhBase = (const char*)(Bhi + (size_t)bn * 256);
    const char* BlBase = (const char*)(Blo + (size_t)bn * 256);

    float acc[2][4][4];
    #pragma unroll
    for (int i = 0; i < 2; i++)
        #pragma unroll
        for (int j = 0; j < 4; j++)
            #pragma unroll
            for (int k = 0; k < 4; k++) acc[i][j][k] = 0.f;

    float4 a_st[8];
    auto stageA = [&](int c) {
        #pragma unroll
        for (int j = 0; j < 8; j++)
            a_st[j] = *(const float4*)(Abase + c * 64 + j * 4);
    };
    auto issueB = [&](int c, int buf) {
        const uint32_t bb = sb + buf * SM_BUFSZ;
        #pragma unroll
        for (int i = 0; i < 2; i++) {
            int row = i * 32 + brow;                       // 0..63
            uint32_t so = swz128((uint32_t)(row * 128 + bjj * 16));
            size_t go = (size_t)row * 512 + c * 128 + bjj * 16;
            CP_ASYNC16(bb + SB_BH + so, BhBase + go);
            CP_ASYNC16(bb + SB_BL + so, BlBase + go);
        }
        CP_COMMIT();
    };
    auto cvtstoreA = [&](int buf) {
        char* bp = smem + buf * SM_BUFSZ;
        #pragma unroll
        for (int j = 0; j < 4; j++) {
            float4 v0 = a_st[2 * j], v1 = a_st[2 * j + 1];
            float h0,l0,h1,l1,h2,l2,h3,l3,h4,l4,h5,l5,h6,l6,h7,l7;
            bf_split(v0.x,h0,l0); bf_split(v0.y,h1,l1); bf_split(v0.z,h2,l2); bf_split(v0.w,h3,l3);
            bf_split(v1.x,h4,l4); bf_split(v1.y,h5,l5); bf_split(v1.z,h6,l6); bf_split(v1.w,h7,l7);
            uint4 hv = { pack2bf(h0,h1), pack2bf(h2,h3), pack2bf(h4,h5), pack2bf(h6,h7) };
            uint4 lv = { pack2bf(l0,l1), pack2bf(l2,l3), pack2bf(l4,l5), pack2bf(l6,l7) };
            uint32_t off = swz128((uint32_t)(arow * 128 + ahalf * 64 + j * 16));
            *(uint4*)(bp + SB_AH + off) = hv;
            *(uint4*)(bp + SB_AL + off) = lv;
        }
    };
    auto compute = [&](int buf) {
        const uint32_t bb = sb + buf * SM_BUFSZ;
        #pragma unroll
        for (int ks = 0; ks < 4; ks++) {
            uint32_t ah[2][4], al_[2][4];
            #pragma unroll
            for (int mf = 0; mf < 2; mf++) {
                int m_loc = wm + mf * 16 + (lane & 15);
                int kbyte = (ks * 16 + (lane >> 4) * 8) * 2;
                uint32_t off = swz128((uint32_t)(m_loc * 128 + kbyte));
                ldm_x4(ah[mf],  bb + SB_AH + off);
                ldm_x4(al_[mf], bb + SB_AL + off);
            }
            uint32_t bh[4][2], bl[4][2];
            #pragma unroll
            for (int nf = 0; nf < 2; nf++) {
                int g = lane >> 3, r = lane & 7;
                int n_loc = wn + nf * 16 + ((g & 2) << 2) + r;   // +8 for g>=2
                int kbyte = (ks * 16 + (g & 1) * 8) * 2;
                uint32_t off = swz128((uint32_t)(n_loc * 128 + kbyte));
                uint32_t th[4], tl[4];
                ldm_x4(th, bb + SB_BH + off);
                ldm_x4(tl, bb + SB_BL + off);
                bh[2*nf][0]   = th[0]; bh[2*nf][1]   = th[1];
                bh[2*nf+1][0] = th[2]; bh[2*nf+1][1] = th[3];
                bl[2*nf][0]   = tl[0]; bl[2*nf][1]   = tl[1];
                bl[2*nf+1][0] = tl[2]; bl[2*nf+1][1] = tl[3];
            }
            #pragma unroll
            for (int mf = 0; mf < 2; mf++)
                #pragma unroll
                for (int n8 = 0; n8 < 4; n8++) {
                    mma_bf16(acc[mf][n8], ah[mf],  bh[n8]);
                    mma_bf16(acc[mf][n8], al_[mf], bh[n8]);
                    mma_bf16(acc[mf][n8], ah[mf],  bl[n8]);
                }
        }
    };

    // Prologue: fill buffer 0
    stageA(0);
    issueB(0, 0);
    cvtstoreA(0);
    CP_WAIT0();
    __syncthreads();

    for (int c = 0; c < 4; c++) {
        if (c < 3) {
            stageA(c + 1);             // LDGs in flight during compute
            issueB(c + 1, (c + 1) & 1);
        }
        compute(c & 1);
        if (c < 3) {
            cvtstoreA((c + 1) & 1);    // consume LDGs after compute
            CP_WAIT0();
        }
        __syncthreads();
    }

    // Epilogue: direct global stores with bias (bias index = global column)
    #pragma unroll
    for (int mf = 0; mf < 2; mf++) {
        #pragma unroll
        for (int n8 = 0; n8 < 4; n8++) {
            int col = bn + wn + n8 * 8 + (lane & 3) * 2;
            int r0  = bm + wm + mf * 16 + (lane >> 2);
            float b0 = __ldg(bias + col);
            float b1 = __ldg(bias + col + 1);
            float2 v0 = { acc[mf][n8][0] + b0, acc[mf][n8][1] + b1 };
            float2 v1 = { acc[mf][n8][2] + b0, acc[mf][n8][3] + b1 };
            *(float2*)(C + (size_t)r0 * N + col)       = v0;
            *(float2*)(C + (size_t)(r0 + 8) * N + col) = v1;
        }
    }
}

// ---------------------------------------------------------------------------
// Weight prep: transpose to [N][K] and split into bf16 hi/lo
// ---------------------------------------------------------------------------
__global__ void prep_wsplit(const float* __restrict__ W,        // [256][256]
                            __nv_bfloat16* __restrict__ hi,
                            __nv_bfloat16* __restrict__ lo)
{
    int n = blockIdx.x, k = threadIdx.x;
    float x = W[(size_t)k * 256 + n];
    float hf, lf; bf_split(x, hf, lf);
    hi[(size_t)n * 256 + k] = __float2bfloat16_rn(hf);
    lo[(size_t)n * 256 + k] = __float2bfloat16_rn(lf);
}

__global__ void prep_wcomb(const float* __restrict__ W_off,     // [256][64]
                           const float* __restrict__ W_attn,    // [256][32]
                           const float* __restrict__ b_off,
                           const float* __restrict__ b_attn,
                           __nv_bfloat16* __restrict__ hi,
                           __nv_bfloat16* __restrict__ lo,
                           float* __restrict__ bias)
{
    int n = blockIdx.x, k = threadIdx.x;     // n < 128, k < 256
    float x = 0.f;
    if (n < 64)       x = W_off[(size_t)k * 64 + n];
    else if (n < 96)  x = W_attn[(size_t)k * 32 + (n - 64)];
    float hf, lf; bf_split(x, hf, lf);
    hi[(size_t)n * 256 + k] = __float2bfloat16_rn(hf);
    lo[(size_t)n * 256 + k] = __float2bfloat16_rn(lf);
    if (k == 0) bias[n] = (n < 64) ? b_off[n] : ((n < 96) ? b_attn[n - 64] : 0.f);
}

// ---------------------------------------------------------------------------
// Sample: softmax + bilinear gather; projections precomputed in g_proj.
// One CTA of 256 threads per (b,q). Warp h = head h, lane = channel.
// ---------------------------------------------------------------------------
__global__ __launch_bounds__(256)
void sample_kernel(const float* __restrict__ refpts)
{
    const int bq = blockIdx.x;
    const int b  = bq / Q_;
    const int t  = threadIdx.x;

    __shared__ float offs[NH * NP * 2];   // 64
    __shared__ float attn[NH * NP];       // 32

    if (t < 96) {
        float v = g_proj[(size_t)bq * PN + t];
        if (t < 64) offs[t] = v;
        else        attn[t - 64] = v;
    }
    __syncthreads();

    if (t < NH) {
        float m = attn[t * NP];
        #pragma unroll
        for (int p = 1; p < NP; p++) m = fmaxf(m, attn[t * NP + p]);
        float e[NP], s = 0.f;
        #pragma unroll
        for (int p = 0; p < NP; p++) { e[p] = __expf(attn[t * NP + p] - m); s += e[p]; }
        float inv = 1.f / s;
        #pragma unroll
        for (int p = 0; p < NP; p++) attn[t * NP + p] = e[p] * inv;
    }
    __syncthreads();

    const int h = t >> 5;
    const int d = t & 31;
    const float rx = refpts[(size_t)bq * 2 + 0];
    const float ry = refpts[(size_t)bq * 2 + 1];
    const float* vb = g_values + (size_t)b * HW * D_ + h * DH + d;

    float acc = 0.f;
    #pragma unroll
    for (int p = 0; p < NP; p++) {
        float lx = fminf(fmaxf(rx + offs[(h * NP + p) * 2 + 0], 0.f), 1.f);
        float ly = fminf(fmaxf(ry + offs[(h * NP + p) * 2 + 1], 0.f), 1.f);
        float sx = lx * (float)(Ww - 1);
        float sy = ly * (float)(Hh - 1);
        int x0 = min(max((int)floorf(sx), 0), Ww - 1);
        int y0 = min(max((int)floorf(sy), 0), Hh - 1);
        int x1 = min(x0 + 1, Ww - 1);
        int y1 = min(y0 + 1, Hh - 1);
        float wx1 = sx - (float)x0, wx0 = 1.f - wx1;
        float wy1 = sy - (float)y0, wy0 = 1.f - wy1;

        float g00 = vb[(size_t)(y0 * Ww + x0) * D_];
        float g01 = vb[(size_t)(y1 * Ww + x0) * D_];
        float g10 = vb[(size_t)(y0 * Ww + x1) * D_];
        float g11 = vb[(size_t)(y1 * Ww + x1) * D_];

        float bil = g00 * (wx0 * wy0) + g01 * (wx0 * wy1)
                  + g10 * (wx1 * wy0) + g11 * (wx1 * wy1);
        acc = fmaf(attn[h * NP + p], bil, acc);
    }
    g_result[(size_t)bq * D_ + t] = acc;
}

// ---------------------------------------------------------------------------
// kernel_launch
// Inputs: 0=query 1=reference_points 2=input_flatten 3=h 4=w
//   5=W_off 6=b_off 7=W_attn 8=b_attn 9=W_val 10=b_val 11=W_out 12=b_out
// ---------------------------------------------------------------------------
extern "C" void kernel_launch(void* const* d_in, const int* in_sizes, int n_in,
                              void* d_out, int out_size)
{
    const float* query    = (const float*)d_in[0];
    const float* refpts   = (const float*)d_in[1];
    const float* in_flat  = (const float*)d_in[2];
    const float* W_off    = (const float*)d_in[5];
    const float* b_off    = (const float*)d_in[6];
    const float* W_attn   = (const float*)d_in[7];
    const float* b_attn   = (const float*)d_in[8];
    const float* W_val    = (const float*)d_in[9];
    const float* b_val    = (const float*)d_in[10];
    const float* W_out    = (const float*)d_in[11];
    const float* b_out    = (const float*)d_in[12];
    float* out = (float*)d_out;

    float *values_p, *result_p, *proj_p, *biasc_p;
    __nv_bfloat16 *wvh, *wvl, *woh, *wol, *wch, *wcl;
    cudaGetSymbolAddress((void**)&values_p, g_values);
    cudaGetSymbolAddress((void**)&result_p, g_result);
    cudaGetSymbolAddress((void**)&proj_p,   g_proj);
    cudaGetSymbolAddress((void**)&biasc_p,  g_bias_comb);
    cudaGetSymbolAddress((void**)&wvh, g_WvalT_hi);
    cudaGetSymbolAddress((void**)&wvl, g_WvalT_lo);
    cudaGetSymbolAddress((void**)&woh, g_WoutT_hi);
    cudaGetSymbolAddress((void**)&wol, g_WoutT_lo);
    cudaGetSymbolAddress((void**)&wch, g_Wcomb_hi);
    cudaGetSymbolAddress((void**)&wcl, g_Wcomb_lo);

    cudaFuncSetAttribute(gemm_bf16x3, cudaFuncAttributeMaxDynamicSharedMemorySize, SMEM_GEMM);

    // 0) weight prep (tiny)
    prep_wsplit<<<256, 256>>>(W_val, wvh, wvl);
    prep_wsplit<<<256, 256>>>(W_out, woh, wol);
    prep_wcomb<<<128, 256>>>(W_off, W_attn, b_off, b_attn, wch, wcl, biasc_p);

    // 1) projections: g_proj[16384,128] = query @ Wcomb^T + bias_comb
    {
        dim3 grid(BQ / 128, PN / 64);    // (128, 2)
        gemm_bf16x3<<<grid, 256, SMEM_GEMM>>>(query, wch, wcl, biasc_p, proj_p, PN);
    }

    // 2) values: g_values[80000,256] = input_flatten @ W_val + b_val
    {
        dim3 grid((B_ * HW) / 128, D_ / 64);   // (625, 4)
        gemm_bf16x3<<<grid, 256, SMEM_GEMM>>>(in_flat, wvh, wvl, b_val, values_p, D_);
    }

    // 3) softmax + bilinear sampling -> g_result[16384,256]
    sample_kernel<<<BQ, 256>>>(refpts);

    // 4) out = g_result @ W_out + b_out
    {
        dim3 grid(BQ / 128, D_ / 64);    // (128, 4)
        gemm_bf16x3<<<grid, 256, SMEM_GEMM>>>(result_p, woh, wol, b_out, out, D_);
    }
}

// round 11
// speedup vs baseline: 1.2775x; 1.1437x over previous
#include <cuda_runtime.h>
#include <cuda_bf16.h>
#include <math.h>
#include <cstdint>

// R11: R9/R10 (named 2-warp barriers) container-failed twice in a row; the
// R7->R8 precedent showed one resubmit clears a flake, so two identical
// failures implicate the named barrier. This version achieves the same
// "no full-CTA sync in the mainloop" goal with WARP-PRIVATE A staging:
// warp tile 16x128, each warp stages/converts its own 16 A rows into its
// own smem buffer, synchronized only by __syncwarp(). B (hi+lo, full K)
// is resident in smem behind the single prologue __syncthreads (construct
// validated in R5/R6/R8).

// ---------------------------------------------------------------------------
// Problem constants (fixed by the dataset's setup_inputs)
// ---------------------------------------------------------------------------
constexpr int B_  = 8;
constexpr int Q_  = 2048;
constexpr int D_  = 256;
constexpr int Hh  = 100;
constexpr int Ww  = 100;
constexpr int HW  = Hh * Ww;       // 10000
constexpr int NH  = 8;
constexpr int NP  = 4;
constexpr int DH  = D_ / NH;       // 32
constexpr int BQ  = B_ * Q_;       // 16384
constexpr int PN  = 128;           // padded projection width (64 off + 32 attn + pad)

// Scratch (allocation-free rule: __device__ globals)
__device__ float         g_values[(size_t)B_ * HW * D_];   // 81.9 MB
__device__ float         g_result[(size_t)BQ * D_];        // 16.8 MB
__device__ float         g_proj[(size_t)BQ * PN];          // 8.4 MB
__device__ __nv_bfloat16 g_WvalT_hi[D_ * D_], g_WvalT_lo[D_ * D_];
__device__ __nv_bfloat16 g_WoutT_hi[D_ * D_], g_WoutT_lo[D_ * D_];
__device__ __nv_bfloat16 g_Wcomb_hi[PN * D_], g_Wcomb_lo[PN * D_];
__device__ float         g_bias_comb[PN];

// ---------------------------------------------------------------------------
// Helpers
// ---------------------------------------------------------------------------
__device__ __forceinline__ uint32_t smem_u32(const void* p) {
    uint32_t a;
    asm("{ .reg .u64 t; cvta.to.shared.u64 t, %1; cvt.u32.u64 %0, t; }" : "=r"(a) : "l"(p));
    return a;
}
// swizzle for 128B-row layouts: 16B-unit ^= (row & 7)
__device__ __forceinline__ uint32_t swz128(uint32_t off) { return off ^ ((off >> 3) & 0x70); }
// swizzle for 512B-row layouts
__device__ __forceinline__ uint32_t swz512(uint32_t off) { return off ^ ((off >> 5) & 0x70); }

__device__ __forceinline__ uint32_t pack2bf(float a, float b) {   // a -> low half
    __nv_bfloat162 t = __floats2bfloat162_rn(a, b);
    return *reinterpret_cast<uint32_t*>(&t);
}
__device__ __forceinline__ void bf_split(float x, float& hf, float& lf) {
    __nv_bfloat16 h = __float2bfloat16_rn(x);
    hf = __bfloat162float(h);
    lf = x - hf;
}

__device__ __forceinline__ void ldm_x4(uint32_t* r, uint32_t addr) {
    asm volatile("ldmatrix.sync.aligned.m8n8.x4.shared.b16 {%0,%1,%2,%3}, [%4];"
        : "=r"(r[0]), "=r"(r[1]), "=r"(r[2]), "=r"(r[3]) : "r"(addr));
}
__device__ __forceinline__ void mma_bf16(float* d, const uint32_t* a, const uint32_t* b) {
    asm volatile("mma.sync.aligned.m16n8k16.row.col.f32.bf16.bf16.f32 "
        "{%0,%1,%2,%3}, {%4,%5,%6,%7}, {%8,%9}, {%0,%1,%2,%3};"
        : "+f"(d[0]), "+f"(d[1]), "+f"(d[2]), "+f"(d[3])
        : "r"(a[0]), "r"(a[1]), "r"(a[2]), "r"(a[3]), "r"(b[0]), "r"(b[1]));
}

// ---------------------------------------------------------------------------
// bf16x3 GEMM via mma.sync: C[M,N] = A[M,256] @ (Bhi+Blo)[N,256]^T + bias
//   BM=128, BN=128, 8 warps, warp tile 16x128.
//   B (hi+lo, full K=256) resident in SMEM (swz512), loaded once (prologue
//   __syncthreads). A is staged per-warp into warp-private buffers and
//   synchronized with __syncwarp() only. 3-term split: ah*bh+al*bh+ah*bl.
// SMEM: BH 64KB | BL 64KB | A: 8 warps x 2 bufs x (hi 2KB + lo 2KB) = 64KB.
// ---------------------------------------------------------------------------
constexpr int SB_BH = 0;
constexpr int SB_BL = 65536;
constexpr int SB_A  = 131072;          // + w*8192 + buf*4096 ; lo at +2048
constexpr int SMEM_GEMM = 196608;

__global__ __launch_bounds__(256, 1)
void gemm_bf16x3(const float* __restrict__ A,
                 const __nv_bfloat16* __restrict__ Bhi,
                 const __nv_bfloat16* __restrict__ Blo,
                 const float* __restrict__ bias,
                 float* __restrict__ C, int N)
{
    extern __shared__ char smem[];
    const uint32_t sb = smem_u32(smem);
    const int tid  = threadIdx.x;
    const int bm   = blockIdx.x * 128;
    const int bn   = blockIdx.y * 128;
    const int w    = tid >> 5;
    const int lane = tid & 31;
    const int wm   = w * 16;                 // this warp's 16 M-rows

    // Warp-private A staging: 32 lanes cover 16 rows x 2 halves (32 floats/lane)
    const int lr    = lane >> 1;             // local row 0..15
    const int ahalf = lane & 1;              // 0 or 1 (32-float half)
    const float* Abase = A + (size_t)(bm + wm + lr) * 256 + ahalf * 32;
    const uint32_t aWarpBase = sb + SB_A + w * 8192;

    float acc[16][4];
    #pragma unroll
    for (int j = 0; j < 16; j++)
        #pragma unroll
        for (int k = 0; k < 4; k++) acc[j][k] = 0.f;

    // ---- Prologue: load full B (hi+lo, [128 rows][512B]) into resident SMEM ----
    {
        const char* BhB = (const char*)(Bhi + (size_t)bn * 256);
        const char* BlB = (const char*)(Blo + (size_t)bn * 256);
        #pragma unroll
        for (int i = 0; i < 16; i++) {
            int u = i * 256 + tid;
            uint32_t off = (uint32_t)u * 16;
            uint4 hv = *(const uint4*)(BhB + off);
            uint4 lv = *(const uint4*)(BlB + off);
            uint32_t so = swz512(off);
            *(uint4*)(smem + SB_BH + so) = hv;
            *(uint4*)(smem + SB_BL + so) = lv;
        }
    }
    __syncthreads();   // only full-CTA sync in the kernel

    float4 a_st[8];
    auto stageA = [&](int c) {
        #pragma unroll
        for (int j = 0; j < 8; j++)
            a_st[j] = *(const float4*)(Abase + c * 64 + j * 4);
    };
    auto cvtstoreA = [&](int buf) {
        char* bp = smem + SB_A + w * 8192 + buf * 4096;
        #pragma unroll
        for (int j = 0; j < 4; j++) {
            float4 v0 = a_st[2 * j], v1 = a_st[2 * j + 1];
            float h0,l0,h1,l1,h2,l2,h3,l3,h4,l4,h5,l5,h6,l6,h7,l7;
            bf_split(v0.x,h0,l0); bf_split(v0.y,h1,l1); bf_split(v0.z,h2,l2); bf_split(v0.w,h3,l3);
            bf_split(v1.x,h4,l4); bf_split(v1.y,h5,l5); bf_split(v1.z,h6,l6); bf_split(v1.w,h7,l7);
            uint4 hv = { pack2bf(h0,h1), pack2bf(h2,h3), pack2bf(h4,h5), pack2bf(h6,h7) };
            uint4 lv = { pack2bf(l0,l1), pack2bf(l2,l3), pack2bf(l4,l5), pack2bf(l6,l7) };
            uint32_t off = swz128((uint32_t)(lr * 128 + ahalf * 64 + j * 16));
            *(uint4*)(bp + off)        = hv;
            *(uint4*)(bp + 2048 + off) = lv;
        }
    };
    auto compute = [&](int c, int buf) {
        const uint32_t aA = aWarpBase + buf * 4096;
        #pragma unroll
        for (int ks = 0; ks < 4; ks++) {
            // A fragment: m16 x k16 (hi and lo)
            uint32_t ah[4], al_[4];
            {
                int m_loc = lane & 15;
                int kbyte = (ks * 16 + (lane >> 4) * 8) * 2;
                uint32_t off = swz128((uint32_t)(m_loc * 128 + kbyte));
                ldm_x4(ah,  aA + off);
                ldm_x4(al_, aA + 2048 + off);
            }
            // B fragments: 8 x (n16 x k16), interleaved with MMA to bound regs
            #pragma unroll
            for (int nf = 0; nf < 8; nf++) {
                int g = lane >> 3, r = lane & 7;
                int n_loc = nf * 16 + ((g & 2) << 2) + r;        // +8 for g>=2
                int kbyte = c * 128 + ks * 32 + (g & 1) * 16;
                uint32_t off = swz512((uint32_t)(n_loc * 512 + kbyte));
                uint32_t th[4], tl[4];
                ldm_x4(th, sb + SB_BH + off);
                ldm_x4(tl, sb + SB_BL + off);
                uint32_t b0h[2] = { th[0], th[1] }, b1h[2] = { th[2], th[3] };
                uint32_t b0l[2] = { tl[0], tl[1] }, b1l[2] = { tl[2], tl[3] };
                mma_bf16(acc[2*nf],   ah,  b0h);
                mma_bf16(acc[2*nf],   al_, b0h);
                mma_bf16(acc[2*nf],   ah,  b0l);
                mma_bf16(acc[2*nf+1], ah,  b1h);
                mma_bf16(acc[2*nf+1], al_, b1h);
                mma_bf16(acc[2*nf+1], ah,  b1l);
            }
        }
    };

    // Prologue for A buffer 0 (warp-scoped)
    stageA(0);
    cvtstoreA(0);
    __syncwarp();

    for (int c = 0; c < 4; c++) {
        if (c < 3) stageA(c + 1);          // LDGs in flight during compute
        compute(c, c & 1);
        if (c < 3) {
            cvtstoreA((c + 1) & 1);        // consume LDGs after compute
            __syncwarp();
        }
    }

    // Epilogue: direct global stores with bias (bias index = global column)
    #pragma unroll
    for (int n8 = 0; n8 < 16; n8++) {
        int col = bn + n8 * 8 + (lane & 3) * 2;
        int r0  = bm + wm + (lane >> 2);
        float b0 = __ldg(bias + col);
        float b1 = __ldg(bias + col + 1);
        float2 v0 = { acc[n8][0] + b0, acc[n8][1] + b1 };
        float2 v1 = { acc[n8][2] + b0, acc[n8][3] + b1 };
        *(float2*)(C + (size_t)r0 * N + col)       = v0;
        *(float2*)(C + (size_t)(r0 + 8) * N + col) = v1;
    }
}

// ---------------------------------------------------------------------------
// Weight prep: transpose to [N][K] and split into bf16 hi/lo
// ---------------------------------------------------------------------------
__global__ void prep_wsplit(const float* __restrict__ W,        // [256][256]
                            __nv_bfloat16* __restrict__ hi,
                            __nv_bfloat16* __restrict__ lo)
{
    int n = blockIdx.x, k = threadIdx.x;
    float x = W[(size_t)k * 256 + n];
    float hf, lf; bf_split(x, hf, lf);
    hi[(size_t)n * 256 + k] = __float2bfloat16_rn(hf);
    lo[(size_t)n * 256 + k] = __float2bfloat16_rn(lf);
}

__global__ void prep_wcomb(const float* __restrict__ W_off,     // [256][64]
                           const float* __restrict__ W_attn,    // [256][32]
                           const float* __restrict__ b_off,
                           const float* __restrict__ b_attn,
                           __nv_bfloat16* __restrict__ hi,
                           __nv_bfloat16* __restrict__ lo,
                           float* __restrict__ bias)
{
    int n = blockIdx.x, k = threadIdx.x;     // n < 128, k < 256
    float x = 0.f;
    if (n < 64)       x = W_off[(size_t)k * 64 + n];
    else if (n < 96)  x = W_attn[(size_t)k * 32 + (n - 64)];
    float hf, lf; bf_split(x, hf, lf);
    hi[(size_t)n * 256 + k] = __float2bfloat16_rn(hf);
    lo[(size_t)n * 256 + k] = __float2bfloat16_rn(lf);
    if (k == 0) bias[n] = (n < 64) ? b_off[n] : ((n < 96) ? b_attn[n - 64] : 0.f);
}

// ---------------------------------------------------------------------------
// Sample: softmax + bilinear gather, BARRIER-FREE.
// One CTA of 256 threads per (b,q). Warp h = head h, lane = channel.
// ---------------------------------------------------------------------------
__global__ __launch_bounds__(256)
void sample_kernel(const float* __restrict__ refpts)
{
    const int bq = blockIdx.x;
    const int b  = bq / Q_;
    const int t  = threadIdx.x;
    const int h  = t >> 5;
    const int d  = t & 31;

    const float* pr = g_proj + (size_t)bq * PN;

    // attention logits -> softmax (redundant per thread; 4 values)
    float a0 = pr[64 + h * NP + 0];
    float a1 = pr[64 + h * NP + 1];
    float a2 = pr[64 + h * NP + 2];
    float a3 = pr[64 + h * NP + 3];
    float m  = fmaxf(fmaxf(a0, a1), fmaxf(a2, a3));
    float e0 = __expf(a0 - m), e1 = __expf(a1 - m);
    float e2 = __expf(a2 - m), e3 = __expf(a3 - m);
    float inv = 1.f / (e0 + e1 + e2 + e3);
    float wgt[NP] = { e0 * inv, e1 * inv, e2 * inv, e3 * inv };

    const float rx = refpts[(size_t)bq * 2 + 0];
    const float ry = refpts[(size_t)bq * 2 + 1];
    const float* vb = g_values + (size_t)b * HW * D_ + h * DH + d;

    float acc = 0.f;
    #pragma unroll
    for (int p = 0; p < NP; p++) {
        float ox = pr[(h * NP + p) * 2 + 0];
        float oy = pr[(h * NP + p) * 2 + 1];
        float lx = fminf(fmaxf(rx + ox, 0.f), 1.f);
        float ly = fminf(fmaxf(ry + oy, 0.f), 1.f);
        float sx = lx * (float)(Ww - 1);
        float sy = ly * (float)(Hh - 1);
        int x0 = min(max((int)floorf(sx), 0), Ww - 1);
        int y0 = min(max((int)floorf(sy), 0), Hh - 1);
        int x1 = min(x0 + 1, Ww - 1);
        int y1 = min(y0 + 1, Hh - 1);
        float wx1 = sx - (float)x0, wx0 = 1.f - wx1;
        float wy1 = sy - (float)y0, wy0 = 1.f - wy1;

        float g00 = vb[(size_t)(y0 * Ww + x0) * D_];
        float g01 = vb[(size_t)(y1 * Ww + x0) * D_];
        float g10 = vb[(size_t)(y0 * Ww + x1) * D_];
        float g11 = vb[(size_t)(y1 * Ww + x1) * D_];

        float bil = g00 * (wx0 * wy0) + g01 * (wx0 * wy1)
                  + g10 * (wx1 * wy0) + g11 * (wx1 * wy1);
        acc = fmaf(wgt[p], bil, acc);
    }
    g_result[(size_t)bq * D_ + t] = acc;
}

// ---------------------------------------------------------------------------
// kernel_launch
// Inputs: 0=query 1=reference_points 2=input_flatten 3=h 4=w
//   5=W_off 6=b_off 7=W_attn 8=b_attn 9=W_val 10=b_val 11=W_out 12=b_out
// ---------------------------------------------------------------------------
extern "C" void kernel_launch(void* const* d_in, const int* in_sizes, int n_in,
                              void* d_out, int out_size)
{
    const float* query    = (const float*)d_in[0];
    const float* refpts   = (const float*)d_in[1];
    const float* in_flat  = (const float*)d_in[2];
    const float* W_off    = (const float*)d_in[5];
    const float* b_off    = (const float*)d_in[6];
    const float* W_attn   = (const float*)d_in[7];
    const float* b_attn   = (const float*)d_in[8];
    const float* W_val    = (const float*)d_in[9];
    const float* b_val    = (const float*)d_in[10];
    const float* W_out    = (const float*)d_in[11];
    const float* b_out    = (const float*)d_in[12];
    float* out = (float*)d_out;

    float *values_p, *result_p, *proj_p, *biasc_p;
    __nv_bfloat16 *wvh, *wvl, *woh, *wol, *wch, *wcl;
    cudaGetSymbolAddress((void**)&values_p, g_values);
    cudaGetSymbolAddress((void**)&result_p, g_result);
    cudaGetSymbolAddress((void**)&proj_p,   g_proj);
    cudaGetSymbolAddress((void**)&biasc_p,  g_bias_comb);
    cudaGetSymbolAddress((void**)&wvh, g_WvalT_hi);
    cudaGetSymbolAddress((void**)&wvl, g_WvalT_lo);
    cudaGetSymbolAddress((void**)&woh, g_WoutT_hi);
    cudaGetSymbolAddress((void**)&wol, g_WoutT_lo);
    cudaGetSymbolAddress((void**)&wch, g_Wcomb_hi);
    cudaGetSymbolAddress((void**)&wcl, g_Wcomb_lo);

    cudaFuncSetAttribute(gemm_bf16x3, cudaFuncAttributeMaxDynamicSharedMemorySize, SMEM_GEMM);

    // 0) weight prep (tiny)
    prep_wsplit<<<256, 256>>>(W_val, wvh, wvl);
    prep_wsplit<<<256, 256>>>(W_out, woh, wol);
    prep_wcomb<<<128, 256>>>(W_off, W_attn, b_off, b_attn, wch, wcl, biasc_p);

    // 1) projections: g_proj[16384,128] = query @ Wcomb^T + bias_comb
    {
        dim3 grid(BQ / 128, 1);
        gemm_bf16x3<<<grid, 256, SMEM_GEMM>>>(query, wch, wcl, biasc_p, proj_p, PN);
    }

    // 2) values: g_values[80000,256] = input_flatten @ W_val + b_val
    {
        dim3 grid((B_ * HW) / 128, 2);
        gemm_bf16x3<<<grid, 256, SMEM_GEMM>>>(in_flat, wvh, wvl, b_val, values_p, D_);
    }

    // 3) softmax + bilinear sampling (barrier-free) -> g_result[16384,256]
    sample_kernel<<<BQ, 256>>>(refpts);

    // 4) out = g_result @ W_out + b_out
    {
        dim3 grid(BQ / 128, 2);
        gemm_bf16x3<<<grid, 256, SMEM_GEMM>>>(result_p, woh, wol, b_out, out, D_);
    }
}

// round 13
// speedup vs baseline: 1.2880x; 1.0082x over previous
#include <cuda_runtime.h>
#include <cuda_bf16.h>
#include <math.h>
#include <cstdint>

// R13 == R12 verbatim re-run. R12 hit "GB300 container failed twice" — the
// same signature seen in R2/R7/R9/R10, and the R7->R8 byte-identical resubmit
// proved it occurs on correct kernels (empirical flake rate ~38%). Audit of
// R12's persistent M-tile sweep found no hang/fault mechanism (bounded loops,
// guarded next-tile stage, in-bounds addresses, no cross-warp coupling after
// the prologue). Per the pre-committed protocol: one verbatim resubmit to
// disambiguate; if it fails again, fall back to R11 + persistent sweep on the
// values GEMM only.

// ---------------------------------------------------------------------------
// Problem constants (fixed by the dataset's setup_inputs)
// ---------------------------------------------------------------------------
constexpr int B_  = 8;
constexpr int Q_  = 2048;
constexpr int D_  = 256;
constexpr int Hh  = 100;
constexpr int Ww  = 100;
constexpr int HW  = Hh * Ww;       // 10000
constexpr int NH  = 8;
constexpr int NP  = 4;
constexpr int DH  = D_ / NH;       // 32
constexpr int BQ  = B_ * Q_;       // 16384
constexpr int PN  = 128;           // padded projection width (64 off + 32 attn + pad)

// Scratch (allocation-free rule: __device__ globals)
__device__ float         g_values[(size_t)B_ * HW * D_];   // 81.9 MB
__device__ float         g_result[(size_t)BQ * D_];        // 16.8 MB
__device__ float         g_proj[(size_t)BQ * PN];          // 8.4 MB
__device__ __nv_bfloat16 g_WvalT_hi[D_ * D_], g_WvalT_lo[D_ * D_];
__device__ __nv_bfloat16 g_WoutT_hi[D_ * D_], g_WoutT_lo[D_ * D_];
__device__ __nv_bfloat16 g_Wcomb_hi[PN * D_], g_Wcomb_lo[PN * D_];
__device__ float         g_bias_comb[PN];

// ---------------------------------------------------------------------------
// Helpers
// ---------------------------------------------------------------------------
__device__ __forceinline__ uint32_t smem_u32(const void* p) {
    uint32_t a;
    asm("{ .reg .u64 t; cvta.to.shared.u64 t, %1; cvt.u32.u64 %0, t; }" : "=r"(a) : "l"(p));
    return a;
}
// swizzle for 128B-row layouts: 16B-unit ^= (row & 7)
__device__ __forceinline__ uint32_t swz128(uint32_t off) { return off ^ ((off >> 3) & 0x70); }
// swizzle for 512B-row layouts
__device__ __forceinline__ uint32_t swz512(uint32_t off) { return off ^ ((off >> 5) & 0x70); }

__device__ __forceinline__ uint32_t pack2bf(float a, float b) {   // a -> low half
    __nv_bfloat162 t = __floats2bfloat162_rn(a, b);
    return *reinterpret_cast<uint32_t*>(&t);
}
__device__ __forceinline__ void bf_split(float x, float& hf, float& lf) {
    __nv_bfloat16 h = __float2bfloat16_rn(x);
    hf = __bfloat162float(h);
    lf = x - hf;
}

__device__ __forceinline__ void ldm_x4(uint32_t* r, uint32_t addr) {
    asm volatile("ldmatrix.sync.aligned.m8n8.x4.shared.b16 {%0,%1,%2,%3}, [%4];"
        : "=r"(r[0]), "=r"(r[1]), "=r"(r[2]), "=r"(r[3]) : "r"(addr));
}
__device__ __forceinline__ void mma_bf16(float* d, const uint32_t* a, const uint32_t* b) {
    asm volatile("mma.sync.aligned.m16n8k16.row.col.f32.bf16.bf16.f32 "
        "{%0,%1,%2,%3}, {%4,%5,%6,%7}, {%8,%9}, {%0,%1,%2,%3};"
        : "+f"(d[0]), "+f"(d[1]), "+f"(d[2]), "+f"(d[3])
        : "r"(a[0]), "r"(a[1]), "r"(a[2]), "r"(a[3]), "r"(b[0]), "r"(b[1]));
}

// ---------------------------------------------------------------------------
// Persistent bf16x3 GEMM via mma.sync:
//   C[M,N] = A[M,256] @ (Bhi+Blo)[N,256]^T + bias
//   BM=128, BN=128, 8 warps, warp tile 16x128.
//   B (hi+lo, full K=256) resident in SMEM, loaded ONCE per CTA; each CTA
//   sweeps M-tiles mt = blockIdx.x, +gridDim.x, ... The A-chunk pipeline runs
//   continuously across tiles (last chunk of tile t overlaps chunk 0 stage of
//   tile t+1; epilogue store overlaps next tile's A LDGs).
//   A staged per-warp (warp-private buffers, __syncwarp only).
// SMEM: BH 64KB | BL 64KB | A: 8 warps x 2 bufs x (hi 2KB + lo 2KB) = 64KB.
// ---------------------------------------------------------------------------
constexpr int SB_BH = 0;
constexpr int SB_BL = 65536;
constexpr int SB_A  = 131072;          // + w*8192 + buf*4096 ; lo at +2048
constexpr int SMEM_GEMM = 196608;

__global__ __launch_bounds__(256, 1)
void gemm_bf16x3(const float* __restrict__ A,
                 const __nv_bfloat16* __restrict__ Bhi,
                 const __nv_bfloat16* __restrict__ Blo,
                 const float* __restrict__ bias,
                 float* __restrict__ C, int N, int MTILES)
{
    extern __shared__ char smem[];
    const uint32_t sb = smem_u32(smem);
    const int tid  = threadIdx.x;
    const int bn   = blockIdx.y * 128;
    const int w    = tid >> 5;
    const int lane = tid & 31;
    const int wm   = w * 16;                 // this warp's 16 M-rows (in-tile)

    // Warp-private A staging: 32 lanes cover 16 rows x 2 halves (32 floats/lane)
    const int lr    = lane >> 1;             // local row 0..15
    const int ahalf = lane & 1;              // 0 or 1 (32-float half)
    const uint32_t aWarpBase = sb + SB_A + w * 8192;

    float acc[16][4];
    #pragma unroll
    for (int j = 0; j < 16; j++)
        #pragma unroll
        for (int k = 0; k < 4; k++) acc[j][k] = 0.f;

    // ---- Load full B (hi+lo, [128 rows][512B]) into resident SMEM, ONCE ----
    {
        const char* BhB = (const char*)(Bhi + (size_t)bn * 256);
        const char* BlB = (const char*)(Blo + (size_t)bn * 256);
        #pragma unroll
        for (int i = 0; i < 16; i++) {
            int u = i * 256 + tid;
            uint32_t off = (uint32_t)u * 16;
            uint4 hv = *(const uint4*)(BhB + off);
            uint4 lv = *(const uint4*)(BlB + off);
            uint32_t so = swz512(off);
            *(uint4*)(smem + SB_BH + so) = hv;
            *(uint4*)(smem + SB_BL + so) = lv;
        }
    }
    __syncthreads();   // only full-CTA sync in the kernel

    float4 a_st[8];
    auto stageA = [&](int bm_, int c) {
        const float* p = A + (size_t)(bm_ + wm + lr) * 256 + ahalf * 32 + c * 64;
        #pragma unroll
        for (int j = 0; j < 8; j++)
            a_st[j] = *(const float4*)(p + j * 4);
    };
    auto cvtstoreA = [&](int buf) {
        char* bp = smem + SB_A + w * 8192 + buf * 4096;
        #pragma unroll
        for (int j = 0; j < 4; j++) {
            float4 v0 = a_st[2 * j], v1 = a_st[2 * j + 1];
            float h0,l0,h1,l1,h2,l2,h3,l3,h4,l4,h5,l5,h6,l6,h7,l7;
            bf_split(v0.x,h0,l0); bf_split(v0.y,h1,l1); bf_split(v0.z,h2,l2); bf_split(v0.w,h3,l3);
            bf_split(v1.x,h4,l4); bf_split(v1.y,h5,l5); bf_split(v1.z,h6,l6); bf_split(v1.w,h7,l7);
            uint4 hv = { pack2bf(h0,h1), pack2bf(h2,h3), pack2bf(h4,h5), pack2bf(h6,h7) };
            uint4 lv = { pack2bf(l0,l1), pack2bf(l2,l3), pack2bf(l4,l5), pack2bf(l6,l7) };
            uint32_t off = swz128((uint32_t)(lr * 128 + ahalf * 64 + j * 16));
            *(uint4*)(bp + off)        = hv;
            *(uint4*)(bp + 2048 + off) = lv;
        }
    };
    auto compute = [&](int c, int buf) {
        const uint32_t aA = aWarpBase + buf * 4096;
        #pragma unroll
        for (int ks = 0; ks < 4; ks++) {
            // A fragment: m16 x k16 (hi and lo)
            uint32_t ah[4], al_[4];
            {
                int m_loc = lane & 15;
                int kbyte = (ks * 16 + (lane >> 4) * 8) * 2;
                uint32_t off = swz128((uint32_t)(m_loc * 128 + kbyte));
                ldm_x4(ah,  aA + off);
                ldm_x4(al_, aA + 2048 + off);
            }
            // B fragments: 8 x (n16 x k16), interleaved with MMA to bound regs
            #pragma unroll
            for (int nf = 0; nf < 8; nf++) {
                int g = lane >> 3, r = lane & 7;
                int n_loc = nf * 16 + ((g & 2) << 2) + r;        // +8 for g>=2
                int kbyte = c * 128 + ks * 32 + (g & 1) * 16;
                uint32_t off = swz512((uint32_t)(n_loc * 512 + kbyte));
                uint32_t th[4], tl[4];
                ldm_x4(th, sb + SB_BH + off);
                ldm_x4(tl, sb + SB_BL + off);
                uint32_t b0h[2] = { th[0], th[1] }, b1h[2] = { th[2], th[3] };
                uint32_t b0l[2] = { tl[0], tl[1] }, b1l[2] = { tl[2], tl[3] };
                mma_bf16(acc[2*nf],   ah,  b0h);
                mma_bf16(acc[2*nf],   al_, b0h);
                mma_bf16(acc[2*nf],   ah,  b0l);
                mma_bf16(acc[2*nf+1], ah,  b1h);
                mma_bf16(acc[2*nf+1], al_, b1h);
                mma_bf16(acc[2*nf+1], ah,  b1l);
            }
        }
    };

    // ---- Persistent M-tile sweep with a continuous chunk pipeline ----
    const int M_END = MTILES * 128;
    const int step  = gridDim.x * 128;
    int bm = blockIdx.x * 128;
    if (bm >= M_END) return;

    stageA(bm, 0);
    cvtstoreA(0);
    __syncwarp();

    for (; bm < M_END; bm += step) {
        const int next_bm  = bm + step;
        const bool has_next = next_bm < M_END;

        #pragma unroll
        for (int c = 0; c < 4; c++) {
            if (c < 3)           stageA(bm, c + 1);
            else if (has_next)   stageA(next_bm, 0);
            compute(c, c & 1);
            if (c < 3 || has_next) {
                cvtstoreA((c + 1) & 1);   // (c=3 -> buf 0 for next tile)
                __syncwarp();
            }
        }

        // Epilogue for this tile: store with bias, reset acc. Overlaps the
        // next tile's A LDG latency.
        #pragma unroll
        for (int n8 = 0; n8 < 16; n8++) {
            int col = bn + n8 * 8 + (lane & 3) * 2;
            int r0  = bm + wm + (lane >> 2);
            float b0 = __ldg(bias + col);
            float b1 = __ldg(bias + col + 1);
            float2 v0 = { acc[n8][0] + b0, acc[n8][1] + b1 };
            float2 v1 = { acc[n8][2] + b0, acc[n8][3] + b1 };
            *(float2*)(C + (size_t)r0 * N + col)       = v0;
            *(float2*)(C + (size_t)(r0 + 8) * N + col) = v1;
            acc[n8][0] = 0.f; acc[n8][1] = 0.f;
            acc[n8][2] = 0.f; acc[n8][3] = 0.f;
        }
    }
}

// ---------------------------------------------------------------------------
// Weight prep: transpose to [N][K] and split into bf16 hi/lo
// ---------------------------------------------------------------------------
__global__ void prep_wsplit(const float* __restrict__ W,        // [256][256]
                            __nv_bfloat16* __restrict__ hi,
                            __nv_bfloat16* __restrict__ lo)
{
    int n = blockIdx.x, k = threadIdx.x;
    float x = W[(size_t)k * 256 + n];
    float hf, lf; bf_split(x, hf, lf);
    hi[(size_t)n * 256 + k] = __float2bfloat16_rn(hf);
    lo[(size_t)n * 256 + k] = __float2bfloat16_rn(lf);
}

__global__ void prep_wcomb(const float* __restrict__ W_off,     // [256][64]
                           const float* __restrict__ W_attn,    // [256][32]
                           const float* __restrict__ b_off,
                           const float* __restrict__ b_attn,
                           __nv_bfloat16* __restrict__ hi,
                           __nv_bfloat16* __restrict__ lo,
                           float* __restrict__ bias)
{
    int n = blockIdx.x, k = threadIdx.x;     // n < 128, k < 256
    float x = 0.f;
    if (n < 64)       x = W_off[(size_t)k * 64 + n];
    else if (n < 96)  x = W_attn[(size_t)k * 32 + (n - 64)];
    float hf, lf; bf_split(x, hf, lf);
    hi[(size_t)n * 256 + k] = __float2bfloat16_rn(hf);
    lo[(size_t)n * 256 + k] = __float2bfloat16_rn(lf);
    if (k == 0) bias[n] = (n < 64) ? b_off[n] : ((n < 96) ? b_attn[n - 64] : 0.f);
}

// ---------------------------------------------------------------------------
// Sample: softmax + bilinear gather, BARRIER-FREE.
// One CTA of 256 threads per (b,q). Warp h = head h, lane = channel.
// ---------------------------------------------------------------------------
__global__ __launch_bounds__(256)
void sample_kernel(const float* __restrict__ refpts)
{
    const int bq = blockIdx.x;
    const int b  = bq / Q_;
    const int t  = threadIdx.x;
    const int h  = t >> 5;
    const int d  = t & 31;

    const float* pr = g_proj + (size_t)bq * PN;

    // attention logits -> softmax (redundant per thread; 4 values)
    float a0 = pr[64 + h * NP + 0];
    float a1 = pr[64 + h * NP + 1];
    float a2 = pr[64 + h * NP + 2];
    float a3 = pr[64 + h * NP + 3];
    float m  = fmaxf(fmaxf(a0, a1), fmaxf(a2, a3));
    float e0 = __expf(a0 - m), e1 = __expf(a1 - m);
    float e2 = __expf(a2 - m), e3 = __expf(a3 - m);
    float inv = 1.f / (e0 + e1 + e2 + e3);
    float wgt[NP] = { e0 * inv, e1 * inv, e2 * inv, e3 * inv };

    const float rx = refpts[(size_t)bq * 2 + 0];
    const float ry = refpts[(size_t)bq * 2 + 1];
    const float* vb = g_values + (size_t)b * HW * D_ + h * DH + d;

    float acc = 0.f;
    #pragma unroll
    for (int p = 0; p < NP; p++) {
        float ox = pr[(h * NP + p) * 2 + 0];
        float oy = pr[(h * NP + p) * 2 + 1];
        float lx = fminf(fmaxf(rx + ox, 0.f), 1.f);
        float ly = fminf(fmaxf(ry + oy, 0.f), 1.f);
        float sx = lx * (float)(Ww - 1);
        float sy = ly * (float)(Hh - 1);
        int x0 = min(max((int)floorf(sx), 0), Ww - 1);
        int y0 = min(max((int)floorf(sy), 0), Hh - 1);
        int x1 = min(x0 + 1, Ww - 1);
        int y1 = min(y0 + 1, Hh - 1);
        float wx1 = sx - (float)x0, wx0 = 1.f - wx1;
        float wy1 = sy - (float)y0, wy0 = 1.f - wy1;

        float g00 = vb[(size_t)(y0 * Ww + x0) * D_];
        float g01 = vb[(size_t)(y1 * Ww + x0) * D_];
        float g10 = vb[(size_t)(y0 * Ww + x1) * D_];
        float g11 = vb[(size_t)(y1 * Ww + x1) * D_];

        float bil = g00 * (wx0 * wy0) + g01 * (wx0 * wy1)
                  + g10 * (wx1 * wy0) + g11 * (wx1 * wy1);
        acc = fmaf(wgt[p], bil, acc);
    }
    g_result[(size_t)bq * D_ + t] = acc;
}

// ---------------------------------------------------------------------------
// kernel_launch
// Inputs: 0=query 1=reference_points 2=input_flatten 3=h 4=w
//   5=W_off 6=b_off 7=W_attn 8=b_attn 9=W_val 10=b_val 11=W_out 12=b_out
// ---------------------------------------------------------------------------
extern "C" void kernel_launch(void* const* d_in, const int* in_sizes, int n_in,
                              void* d_out, int out_size)
{
    const float* query    = (const float*)d_in[0];
    const float* refpts   = (const float*)d_in[1];
    const float* in_flat  = (const float*)d_in[2];
    const float* W_off    = (const float*)d_in[5];
    const float* b_off    = (const float*)d_in[6];
    const float* W_attn   = (const float*)d_in[7];
    const float* b_attn   = (const float*)d_in[8];
    const float* W_val    = (const float*)d_in[9];
    const float* b_val    = (const float*)d_in[10];
    const float* W_out    = (const float*)d_in[11];
    const float* b_out    = (const float*)d_in[12];
    float* out = (float*)d_out;

    float *values_p, *result_p, *proj_p, *biasc_p;
    __nv_bfloat16 *wvh, *wvl, *woh, *wol, *wch, *wcl;
    cudaGetSymbolAddress((void**)&values_p, g_values);
    cudaGetSymbolAddress((void**)&result_p, g_result);
    cudaGetSymbolAddress((void**)&proj_p,   g_proj);
    cudaGetSymbolAddress((void**)&biasc_p,  g_bias_comb);
    cudaGetSymbolAddress((void**)&wvh, g_WvalT_hi);
    cudaGetSymbolAddress((void**)&wvl, g_WvalT_lo);
    cudaGetSymbolAddress((void**)&woh, g_WoutT_hi);
    cudaGetSymbolAddress((void**)&wol, g_WoutT_lo);
    cudaGetSymbolAddress((void**)&wch, g_Wcomb_hi);
    cudaGetSymbolAddress((void**)&wcl, g_Wcomb_lo);

    cudaFuncSetAttribute(gemm_bf16x3, cudaFuncAttributeMaxDynamicSharedMemorySize, SMEM_GEMM);

    // 0) weight prep (tiny)
    prep_wsplit<<<256, 256>>>(W_val, wvh, wvl);
    prep_wsplit<<<256, 256>>>(W_out, woh, wol);
    prep_wcomb<<<128, 256>>>(W_off, W_attn, b_off, b_attn, wch, wcl, biasc_p);

    // 1) projections: g_proj[16384,128] = query @ Wcomb^T + bias_comb
    //    128 M-tiles, 2 per CTA -> grid (64, 1)
    {
        dim3 grid(64, 1);
        gemm_bf16x3<<<grid, 256, SMEM_GEMM>>>(query, wch, wcl, biasc_p, proj_p,
                                              PN, BQ / 128);
    }

    // 2) values: g_values[80000,256] = input_flatten @ W_val + b_val
    //    625 M-tiles, 8-9 per CTA -> grid (74, 2) = 148 CTAs
    {
        dim3 grid(74, 2);
        gemm_bf16x3<<<grid, 256, SMEM_GEMM>>>(in_flat, wvh, wvl, b_val, values_p,
                                              D_, (B_ * HW) / 128);
    }

    // 3) softmax + bilinear sampling (barrier-free) -> g_result[16384,256]
    sample_kernel<<<BQ, 256>>>(refpts);

    // 4) out = g_result @ W_out + b_out
    //    128 M-tiles, 2 per CTA -> grid (64, 2)
    {
        dim3 grid(64, 2);
        gemm_bf16x3<<<grid, 256, SMEM_GEMM>>>(result_p, woh, wol, b_out, out,
                                              D_, BQ / 128);
    }
}